// round 16
// baseline (speedup 1.0000x reference)
#include <cuda_runtime.h>
#include <cuda_bf16.h>
#include <cstdint>

// Problem sizes (fixed)
#define B_ROWS   524288
#define TILE_M   128
#define NTILES   (B_ROWS / TILE_M)   // 4096
#define NTH      256                 // 8 warps: 4 row-groups (32 rows) x 2 n-halves
#define GRID     152                 // persistent CTAs, 1 per SM (GB300 = 152 SMs)
#define NTOT     320                 // [z(64) | interleaved gates i,f,g,o per j (256)]

// ---------------- SMEM layout ----------------
// W frag regions: 40 n-tiles x 8 k-steps x 32 lanes x 8 B = 81920 each
#define OFF_WHI  0
#define OFF_WLO  81920
#define OFF_C    163840              // c0 staged -> c_new in place: 128 rows x 256 B = 32 KB
#define OFF_H    196608              // h_new staging: 32 KB
#define OFF_BIAS 229376              // 320 floats
#define SMEM_BYTES 230656

__device__ __forceinline__ void cpa16(uint32_t dst, const void* src) {
    asm volatile("cp.async.cg.shared.global [%0], [%1], 16;" :: "r"(dst), "l"(src));
}
#define CP_COMMIT() asm volatile("cp.async.commit_group;" ::: "memory")
#define CP_WAIT0()  asm volatile("cp.async.wait_group 0;" ::: "memory")

__device__ __forceinline__ uint32_t smem_u32(const void* p) {
    uint32_t a;
    asm("{ .reg .u64 t; cvta.to.shared.u64 t, %1; cvt.u32.u64 %0, t; }" : "=r"(a) : "l"(p));
    return a;
}

__device__ __forceinline__ void mma16816(float* d, const uint32_t* a, uint32_t b0, uint32_t b1) {
    asm volatile(
        "mma.sync.aligned.m16n8k16.row.col.f32.bf16.bf16.f32 "
        "{%0,%1,%2,%3},{%4,%5,%6,%7},{%8,%9},{%0,%1,%2,%3};"
        : "+f"(d[0]), "+f"(d[1]), "+f"(d[2]), "+f"(d[3])
        : "r"(a[0]), "r"(a[1]), "r"(a[2]), "r"(a[3]), "r"(b0), "r"(b1));
}

// fp32 -> (hi bf16, lo bf16 residual), packed pairs (elem0 in low 16 bits)
__device__ __forceinline__ void split2(float x0, float x1, uint32_t& hi, uint32_t& lo) {
    __nv_bfloat16 h0 = __float2bfloat16(x0);
    __nv_bfloat16 h1 = __float2bfloat16(x1);
    __nv_bfloat16 l0 = __float2bfloat16(x0 - __bfloat162float(h0));
    __nv_bfloat16 l1 = __float2bfloat16(x1 - __bfloat162float(h1));
    hi = (uint32_t)__bfloat16_as_ushort(h0) | ((uint32_t)__bfloat16_as_ushort(h1) << 16);
    lo = (uint32_t)__bfloat16_as_ushort(l0) | ((uint32_t)__bfloat16_as_ushort(l1) << 16);
}

// Reordered weight fetch: col c<64 -> z head (W_o row c); else gate-interleaved:
// gc=c-64, j=gc/4, g=gc%4 (i,f,g,o), source row = g*64+j in stacked W_ih/W_hh.
__device__ __forceinline__ float getW(int c, int k,
                                      const float* Wo, const float* Wih, const float* Whh) {
    if (c < 64) return Wo[c * 128 + k];
    int gc = c - 64, j = gc >> 2, g = gc & 3, r = g * 64 + j;
    return (k < 64) ? Wih[r * 64 + k] : Whh[r * 64 + (k - 64)];
}

// ---------------- z-head pass (NT=8, one 16-row m-tile; unchanged numerics) ----------------
__device__ __forceinline__ void do_pass_z(
    char* sm, const float* __restrict__ bias,
    const uint32_t* ahi, const uint32_t* alo,
    int r0l, int r1l, int q, int l, int row0,
    float* __restrict__ out)
{
    float acc[32];
    #pragma unroll
    for (int i = 0; i < 32; i++) acc[i] = 0.0f;

    #pragma unroll
    for (int s = 0; s < 8; s++) {
        uint32_t bh0[8], bh1[8];
        uint32_t baseH = (uint32_t)s * 256u + (uint32_t)l * 8u;
        #pragma unroll
        for (int tt = 0; tt < 8; tt++) {
            uint2 v = *reinterpret_cast<const uint2*>(sm + OFF_WHI + baseH + ((uint32_t)tt << 11));
            bh0[tt] = v.x; bh1[tt] = v.y;
        }
        #pragma unroll
        for (int tt = 0; tt < 8; tt++)
            mma16816(&acc[4 * tt], &ahi[4 * s], bh0[tt], bh1[tt]);
        #pragma unroll
        for (int tt = 0; tt < 8; tt++) {
            uint2 v = *reinterpret_cast<const uint2*>(sm + OFF_WLO + baseH + ((uint32_t)tt << 11));
            mma16816(&acc[4 * tt], &ahi[4 * s], v.x, v.y);
        }
        #pragma unroll
        for (int tt = 0; tt < 8; tt++)
            mma16816(&acc[4 * tt], &alo[4 * s], bh0[tt], bh1[tt]);
    }

    float m0 = -1e30f, m1 = -1e30f;
    #pragma unroll
    for (int tt = 0; tt < 8; tt++) {
        int cb = 8 * tt + 2 * q;
        acc[4 * tt + 0] += bias[cb];     acc[4 * tt + 1] += bias[cb + 1];
        acc[4 * tt + 2] += bias[cb];     acc[4 * tt + 3] += bias[cb + 1];
        m0 = fmaxf(m0, fmaxf(acc[4 * tt + 0], acc[4 * tt + 1]));
        m1 = fmaxf(m1, fmaxf(acc[4 * tt + 2], acc[4 * tt + 3]));
    }
    m0 = fmaxf(m0, __shfl_xor_sync(0xffffffffu, m0, 1));
    m0 = fmaxf(m0, __shfl_xor_sync(0xffffffffu, m0, 2));
    m1 = fmaxf(m1, __shfl_xor_sync(0xffffffffu, m1, 1));
    m1 = fmaxf(m1, __shfl_xor_sync(0xffffffffu, m1, 2));
    float s0 = 0.0f, s1 = 0.0f;
    #pragma unroll
    for (int tt = 0; tt < 8; tt++) {
        s0 += __expf(acc[4 * tt + 0] - m0) + __expf(acc[4 * tt + 1] - m0);
        s1 += __expf(acc[4 * tt + 2] - m1) + __expf(acc[4 * tt + 3] - m1);
    }
    s0 += __shfl_xor_sync(0xffffffffu, s0, 1);
    s0 += __shfl_xor_sync(0xffffffffu, s0, 2);
    s1 += __shfl_xor_sync(0xffffffffu, s1, 1);
    s1 += __shfl_xor_sync(0xffffffffu, s1, 2);
    float lse0 = m0 + __logf(s0), lse1 = m1 + __logf(s1);
    #pragma unroll
    for (int tt = 0; tt < 8; tt++) {
        int cb = 8 * tt + 2 * q;
        float2 va = make_float2(acc[4 * tt + 0] - lse0, acc[4 * tt + 1] - lse0);
        float2 vb = make_float2(acc[4 * tt + 2] - lse1, acc[4 * tt + 3] - lse1);
        *reinterpret_cast<float2*>(out + (size_t)(row0 + r0l) * 64 + cb) = va;
        *reinterpret_cast<float2*>(out + (size_t)(row0 + r1l) * 64 + cb) = vb;
    }
}

// ---------------- gate epilogue for one 16-row m-tile (4 n-tiles) ----------------
__device__ __forceinline__ void gate_epi(
    float* acc, int tbase, char* sm, const float* __restrict__ bias,
    int rA, int rB, int q)
{
    const bool even = ((q & 1) == 0);
    const float numer = even ? 1.0f : 2.0f;
    const float subv  = even ? 0.0f : 1.0f;
    const float scale = even ? -1.0f : -2.0f;
    #pragma unroll
    for (int tt = 0; tt < 4; tt++) {
        int t  = tbase + tt;
        int cb = 8 * t + 2 * q;
        float v0 = acc[4 * tt + 0] + bias[cb];
        float v1 = acc[4 * tt + 1] + bias[cb + 1];
        float v2 = acc[4 * tt + 2] + bias[cb];
        float v3 = acc[4 * tt + 3] + bias[cb + 1];
        float a0 = numer / (1.0f + __expf(scale * v0)) - subv;
        float a1 = 1.0f / (1.0f + __expf(-v1));
        float a2 = numer / (1.0f + __expf(scale * v2)) - subv;
        float a3 = 1.0f / (1.0f + __expf(-v3));
        float p0 = __shfl_xor_sync(0xffffffffu, a0, 1);
        float p1 = __shfl_xor_sync(0xffffffffu, a1, 1);
        float p2 = __shfl_xor_sync(0xffffffffu, a2, 1);
        float p3 = __shfl_xor_sync(0xffffffffu, a3, 1);
        if (even) {
            int jg = 2 * (t - 8) + (q >> 1);              // global col 0..63
            uint32_t co0 = (uint32_t)rA * 256u + ((uint32_t)((jg >> 2) ^ (rA & 7)) << 4) + ((uint32_t)(jg & 3) << 2);
            uint32_t co1 = (uint32_t)rB * 256u + ((uint32_t)((jg >> 2) ^ (rB & 7)) << 4) + ((uint32_t)(jg & 3) << 2);
            float c00 = *reinterpret_cast<const float*>(sm + OFF_C + co0);    // staged c0 (SMEM)
            float c11 = *reinterpret_cast<const float*>(sm + OFF_C + co1);
            float cn0 = a1 * c00 + a0 * p0;               // f*c + i*g
            float cn1 = a3 * c11 + a2 * p2;
            float hn0 = p1 * (2.0f / (1.0f + __expf(-2.0f * cn0)) - 1.0f);   // o*tanh(cn)
            float hn1 = p3 * (2.0f / (1.0f + __expf(-2.0f * cn1)) - 1.0f);
            *reinterpret_cast<float*>(sm + OFF_C + co0) = cn0;   // c_new in place
            *reinterpret_cast<float*>(sm + OFF_C + co1) = cn1;
            *reinterpret_cast<float*>(sm + OFF_H + co0) = hn0;
            *reinterpret_cast<float*>(sm + OFF_H + co1) = hn1;
        }
    }
}

// ---------------- gate pass (NT=4, M=32: both m-tiles share one W fetch) ----------------
__device__ __forceinline__ void do_pass_g4(
    int tbase, char* sm, const float* __restrict__ bias,
    const uint32_t* ahi0, const uint32_t* alo0,
    const uint32_t* ahi1, const uint32_t* alo1,
    int r0l, int r1l, int r2l, int r3l, int q, int l)
{
    float acc[32];                     // [mt][tt][4]
    #pragma unroll
    for (int i = 0; i < 32; i++) acc[i] = 0.0f;

    uint32_t wh0[2][4], wh1[2][4], wl0[2][4], wl1[2][4];
    const uint32_t base0 = (uint32_t)(tbase * 8) * 256u + (uint32_t)l * 8u;

    // prefetch s=0
    #pragma unroll
    for (int tt = 0; tt < 4; tt++) {
        uint2 vh = *reinterpret_cast<const uint2*>(sm + OFF_WHI + base0 + ((uint32_t)tt << 11));
        uint2 vl = *reinterpret_cast<const uint2*>(sm + OFF_WLO + base0 + ((uint32_t)tt << 11));
        wh0[0][tt] = vh.x; wh1[0][tt] = vh.y;
        wl0[0][tt] = vl.x; wl1[0][tt] = vl.y;
    }

    #pragma unroll
    for (int s = 0; s < 8; s++) {
        const int cur = s & 1, nxt = cur ^ 1;
        if (s < 7) {                                  // prefetch s+1 while s computes
            uint32_t baseN = base0 + (uint32_t)(s + 1) * 256u;
            #pragma unroll
            for (int tt = 0; tt < 4; tt++) {
                uint2 vh = *reinterpret_cast<const uint2*>(sm + OFF_WHI + baseN + ((uint32_t)tt << 11));
                uint2 vl = *reinterpret_cast<const uint2*>(sm + OFF_WLO + baseN + ((uint32_t)tt << 11));
                wh0[nxt][tt] = vh.x; wh1[nxt][tt] = vh.y;
                wl0[nxt][tt] = vl.x; wl1[nxt][tt] = vl.y;
            }
        }
        // 24 HMMA, 8 independent acc chains per term (4 tt x 2 mt)
        #pragma unroll
        for (int tt = 0; tt < 4; tt++)
            mma16816(&acc[4 * tt],      &ahi0[4 * s], wh0[cur][tt], wh1[cur][tt]);
        #pragma unroll
        for (int tt = 0; tt < 4; tt++)
            mma16816(&acc[16 + 4 * tt], &ahi1[4 * s], wh0[cur][tt], wh1[cur][tt]);
        #pragma unroll
        for (int tt = 0; tt < 4; tt++)
            mma16816(&acc[4 * tt],      &ahi0[4 * s], wl0[cur][tt], wl1[cur][tt]);
        #pragma unroll
        for (int tt = 0; tt < 4; tt++)
            mma16816(&acc[16 + 4 * tt], &ahi1[4 * s], wl0[cur][tt], wl1[cur][tt]);
        #pragma unroll
        for (int tt = 0; tt < 4; tt++)
            mma16816(&acc[4 * tt],      &alo0[4 * s], wh0[cur][tt], wh1[cur][tt]);
        #pragma unroll
        for (int tt = 0; tt < 4; tt++)
            mma16816(&acc[16 + 4 * tt], &alo1[4 * s], wh0[cur][tt], wh1[cur][tt]);
    }

    gate_epi(&acc[0],  tbase, sm, bias, r0l, r1l, q);
    gate_epi(&acc[16], tbase, sm, bias, r2l, r3l, q);
}

__global__ __launch_bounds__(NTH, 1) void lstm_hmma_kernel(
    const float* __restrict__ x,   const float* __restrict__ h0,  const float* __restrict__ c0,
    const float* __restrict__ Wih, const float* __restrict__ Whh,
    const float* __restrict__ bih, const float* __restrict__ bhh,
    const float* __restrict__ Wo,  const float* __restrict__ bo,
    float* __restrict__ out)
{
    extern __shared__ __align__(16) char sm[];
    const uint32_t smb = smem_u32(sm);
    const int tid = threadIdx.x;
    const int w    = tid >> 5;
    const int l    = tid & 31;
    const int rg   = w & 3;            // row group 0..3 (32 rows each)
    const int half = w >> 2;           // n-half: 0 = z+gates j0..23, 1 = gates j24..63
    const int gr   = l >> 2;           // group row 0..7
    const int q    = l & 3;            // quad lane 0..3

    // ---- one-time: W -> hi/lo bf16 frags in SMEM (frag-order, conflict-free) ----
    for (int p = tid; p < 40 * 8 * 32; p += NTH) {
        int t = p >> 8, s = (p >> 5) & 7, ln = p & 31;
        int c = 8 * t + (ln >> 2);
        int k0 = 16 * s + 2 * (ln & 3);
        float w00 = getW(c, k0,     Wo, Wih, Whh);
        float w01 = getW(c, k0 + 1, Wo, Wih, Whh);
        float w10 = getW(c, k0 + 8, Wo, Wih, Whh);
        float w11 = getW(c, k0 + 9, Wo, Wih, Whh);
        uint32_t h0p, l0p, h1p, l1p;
        split2(w00, w01, h0p, l0p);   // b0: k0, k0+1
        split2(w10, w11, h1p, l1p);   // b1: k0+8, k0+9
        uint32_t base = (uint32_t)(t * 8 + s) * 256u + (uint32_t)ln * 8u;
        *reinterpret_cast<uint2*>(sm + OFF_WHI + base) = make_uint2(h0p, h1p);
        *reinterpret_cast<uint2*>(sm + OFF_WLO + base) = make_uint2(l0p, l1p);
    }
    // bias, same column reordering
    for (int c = tid; c < NTOT; c += NTH) {
        float b;
        if (c < 64) b = bo[c];
        else { int gc = c - 64, j = gc >> 2, g = gc & 3; b = bih[g * 64 + j] + bhh[g * 64 + j]; }
        reinterpret_cast<float*>(sm + OFF_BIAS)[c] = b;
    }
    __syncthreads();

    const float* bias = reinterpret_cast<const float*>(sm + OFF_BIAS);
    const int r0l = 32 * rg + gr, r1l = r0l + 8, r2l = r0l + 16, r3l = r0l + 24;

    for (int tile = blockIdx.x; tile < NTILES; tile += gridDim.x) {
        const int row0 = tile * TILE_M;

        // ---- c0 cp.async: column-split by half so completion is WARP-LOCAL ----
        // half0: cols j0..23 (chunks 0..5);  half1: cols j24..63 (chunks 6..15)
        if (half == 0) {
            for (int i = l; i < 32 * 6; i += 32) {
                int r16 = i / 6, jc = i % 6;
                int r = 32 * rg + r16;
                uint32_t dst = smb + OFF_C + (uint32_t)r * 256u + ((uint32_t)(jc ^ (r & 7)) << 4);
                cpa16(dst, c0 + (size_t)(row0 + r) * 64 + jc * 4);
            }
        } else {
            for (int i = l; i < 32 * 10; i += 32) {
                int r16 = i / 10, jc = 6 + i % 10;
                int r = 32 * rg + r16;
                uint32_t dst = smb + OFF_C + (uint32_t)r * 256u + ((uint32_t)(jc ^ (r & 7)) << 4);
                cpa16(dst, c0 + (size_t)(row0 + r) * 64 + jc * 4);
            }
        }
        CP_COMMIT();

        // ---- A tile (32 rows/warp): batched LDG (MLP=32 per half) -> hi/lo frags ----
        uint32_t ahi0[32], alo0[32], ahi1[32], alo1[32];
        #pragma unroll
        for (int hb = 0; hb < 2; hb++) {               // hb=0: x (s 0..3), hb=1: h0 (s 4..7)
            const float* bp = hb ? h0 : x;
            const float2* b2 = reinterpret_cast<const float2*>(bp);
            float2 v[32];
            #pragma unroll
            for (int ss = 0; ss < 4; ss++) {           // issue all 32 loads first (deep MLP)
                int kf2 = 8 * ss + q;
                v[8 * ss + 0] = b2[(size_t)(row0 + r0l) * 32 + kf2];
                v[8 * ss + 1] = b2[(size_t)(row0 + r1l) * 32 + kf2];
                v[8 * ss + 2] = b2[(size_t)(row0 + r0l) * 32 + kf2 + 4];
                v[8 * ss + 3] = b2[(size_t)(row0 + r1l) * 32 + kf2 + 4];
                v[8 * ss + 4] = b2[(size_t)(row0 + r2l) * 32 + kf2];
                v[8 * ss + 5] = b2[(size_t)(row0 + r3l) * 32 + kf2];
                v[8 * ss + 6] = b2[(size_t)(row0 + r2l) * 32 + kf2 + 4];
                v[8 * ss + 7] = b2[(size_t)(row0 + r3l) * 32 + kf2 + 4];
            }
            #pragma unroll
            for (int ss = 0; ss < 4; ss++) {
                int s = 4 * hb + ss;
                split2(v[8 * ss + 0].x, v[8 * ss + 0].y, ahi0[4 * s + 0], alo0[4 * s + 0]);
                split2(v[8 * ss + 1].x, v[8 * ss + 1].y, ahi0[4 * s + 1], alo0[4 * s + 1]);
                split2(v[8 * ss + 2].x, v[8 * ss + 2].y, ahi0[4 * s + 2], alo0[4 * s + 2]);
                split2(v[8 * ss + 3].x, v[8 * ss + 3].y, ahi0[4 * s + 3], alo0[4 * s + 3]);
                split2(v[8 * ss + 4].x, v[8 * ss + 4].y, ahi1[4 * s + 0], alo1[4 * s + 0]);
                split2(v[8 * ss + 5].x, v[8 * ss + 5].y, ahi1[4 * s + 1], alo1[4 * s + 1]);
                split2(v[8 * ss + 6].x, v[8 * ss + 6].y, ahi1[4 * s + 2], alo1[4 * s + 2]);
                split2(v[8 * ss + 7].x, v[8 * ss + 7].y, ahi1[4 * s + 3], alo1[4 * s + 3]);
            }
        }

        // ---- warp n-split: half0 = z + gates j0..23, half1 = gates j24..63 ----
        if (half == 0) {
            do_pass_z(sm, bias, ahi0, alo0, r0l, r1l, q, l, row0, out);
            do_pass_z(sm, bias, ahi1, alo1, r2l, r3l, q, l, row0, out);
            CP_WAIT0();                 // this warp's own c0 chunks
            __syncwarp();
            do_pass_g4(8,  sm, bias, ahi0, alo0, ahi1, alo1, r0l, r1l, r2l, r3l, q, l);
            do_pass_g4(12, sm, bias, ahi0, alo0, ahi1, alo1, r0l, r1l, r2l, r3l, q, l);
            do_pass_g4(16, sm, bias, ahi0, alo0, ahi1, alo1, r0l, r1l, r2l, r3l, q, l);
        } else {
            CP_WAIT0();
            __syncwarp();
            do_pass_g4(20, sm, bias, ahi0, alo0, ahi1, alo1, r0l, r1l, r2l, r3l, q, l);
            do_pass_g4(24, sm, bias, ahi0, alo0, ahi1, alo1, r0l, r1l, r2l, r3l, q, l);
            do_pass_g4(28, sm, bias, ahi0, alo0, ahi1, alo1, r0l, r1l, r2l, r3l, q, l);
            do_pass_g4(32, sm, bias, ahi0, alo0, ahi1, alo1, r0l, r1l, r2l, r3l, q, l);
            do_pass_g4(36, sm, bias, ahi0, alo0, ahi1, alo1, r0l, r1l, r2l, r3l, q, l);
        }

        // ---- one barrier, then fully vectorized h/c stores ----
        __syncthreads();
        #pragma unroll
        for (int i = 0; i < 8; i++) {
            int p = tid + i * NTH;                     // 0..2047
            int r = p >> 4, c4 = p & 15;
            uint32_t off = (uint32_t)r * 256u + ((uint32_t)(c4 ^ (r & 7)) << 4);
            float4 hv = *reinterpret_cast<const float4*>(sm + OFF_H + off);
            float4 cv = *reinterpret_cast<const float4*>(sm + OFF_C + off);
            size_t g = (size_t)(row0 + r) * 64 + (size_t)c4 * 4;
            *reinterpret_cast<float4*>(out + (size_t)B_ROWS * 64 + g)     = hv;
            *reinterpret_cast<float4*>(out + (size_t)2 * B_ROWS * 64 + g) = cv;
        }
        __syncthreads();   // protect OFF_H/OFF_C before next tile's cp.async / writes
    }
}

extern "C" void kernel_launch(void* const* d_in, const int* in_sizes, int n_in,
                              void* d_out, int out_size) {
    (void)in_sizes; (void)n_in; (void)out_size;
    cudaFuncSetAttribute(lstm_hmma_kernel, cudaFuncAttributeMaxDynamicSharedMemorySize, SMEM_BYTES);
    lstm_hmma_kernel<<<GRID, NTH, SMEM_BYTES>>>(
        (const float*)d_in[0], (const float*)d_in[1], (const float*)d_in[2],
        (const float*)d_in[3], (const float*)d_in[4],
        (const float*)d_in[5], (const float*)d_in[6],
        (const float*)d_in[7], (const float*)d_in[8],
        (float*)d_out);
}

// round 17
// speedup vs baseline: 1.5800x; 1.5800x over previous
#include <cuda_runtime.h>
#include <cuda_bf16.h>
#include <cstdint>

// Problem sizes (fixed)
#define B_ROWS   524288
#define TILE_M   128
#define NTILES   (B_ROWS / TILE_M)   // 4096
#define NTH      512                 // 16 warps: pairs split the n-dimension
#define GRID     152                 // persistent CTAs, 1 per SM (GB300 = 152 SMs)
#define NTOT     320                 // [z(64) | interleaved gates i,f,g,o per j (256)]

// ---------------- SMEM layout ----------------
// W frags interleaved: per (t,s,lane) one uint4 = (hi_b0, hi_b1, lo_b0, lo_b1)
// 40 n-tiles x 8 k-steps x 32 lanes x 16 B = 163840
#define OFF_W    0
#define OFF_C    163840              // c0 staged -> c_new in place: 128 rows x 256 B = 32 KB
#define OFF_H    196608              // h_new staging: 32 KB
#define OFF_BIAS 229376              // 320 floats
#define SMEM_BYTES 230656

__device__ __forceinline__ void cpa16(uint32_t dst, const void* src) {
    asm volatile("cp.async.cg.shared.global [%0], [%1], 16;" :: "r"(dst), "l"(src));
}
#define CP_COMMIT() asm volatile("cp.async.commit_group;" ::: "memory")
#define CP_WAIT0()  asm volatile("cp.async.wait_group 0;" ::: "memory")

__device__ __forceinline__ uint32_t smem_u32(const void* p) {
    uint32_t a;
    asm("{ .reg .u64 t; cvta.to.shared.u64 t, %1; cvt.u32.u64 %0, t; }" : "=r"(a) : "l"(p));
    return a;
}

__device__ __forceinline__ void mma16816(float* d, const uint32_t* a, uint32_t b0, uint32_t b1) {
    asm volatile(
        "mma.sync.aligned.m16n8k16.row.col.f32.bf16.bf16.f32 "
        "{%0,%1,%2,%3},{%4,%5,%6,%7},{%8,%9},{%0,%1,%2,%3};"
        : "+f"(d[0]), "+f"(d[1]), "+f"(d[2]), "+f"(d[3])
        : "r"(a[0]), "r"(a[1]), "r"(a[2]), "r"(a[3]), "r"(b0), "r"(b1));
}

// fp32 -> (hi bf16, lo bf16 residual), packed pairs (elem0 in low 16 bits)
__device__ __forceinline__ void split2(float x0, float x1, uint32_t& hi, uint32_t& lo) {
    __nv_bfloat16 h0 = __float2bfloat16(x0);
    __nv_bfloat16 h1 = __float2bfloat16(x1);
    __nv_bfloat16 l0 = __float2bfloat16(x0 - __bfloat162float(h0));
    __nv_bfloat16 l1 = __float2bfloat16(x1 - __bfloat162float(h1));
    hi = (uint32_t)__bfloat16_as_ushort(h0) | ((uint32_t)__bfloat16_as_ushort(h1) << 16);
    lo = (uint32_t)__bfloat16_as_ushort(l0) | ((uint32_t)__bfloat16_as_ushort(l1) << 16);
}

// Reordered weight fetch: col c<64 -> z head (W_o row c); else gate-interleaved:
// gc=c-64, j=gc/4, g=gc%4 (i,f,g,o), source row = g*64+j in stacked W_ih/W_hh.
__device__ __forceinline__ float getW(int c, int k,
                                      const float* Wo, const float* Wih, const float* Whh) {
    if (c < 64) return Wo[c * 128 + k];
    int gc = c - 64, j = gc >> 2, g = gc & 3, r = g * 64 + j;
    return (k < 64) ? Wih[r * 64 + k] : Whh[r * 64 + (k - 64)];
}

// ---------------- z-head pass (NT=8, uint4 combined hi/lo loads) ----------------
__device__ __forceinline__ void do_pass_z(
    char* sm, const float* __restrict__ bias,
    const uint32_t* ahi, const uint32_t* alo,
    int r0l, int r1l, int q, int l, int row0,
    float* __restrict__ out)
{
    float acc[32];
    #pragma unroll
    for (int i = 0; i < 32; i++) acc[i] = 0.0f;

    #pragma unroll
    for (int s = 0; s < 8; s++) {
        uint4 wv[8];
        uint32_t baseH = (uint32_t)s * 512u + (uint32_t)l * 16u;
        #pragma unroll
        for (int tt = 0; tt < 8; tt++)
            wv[tt] = *reinterpret_cast<const uint4*>(sm + OFF_W + baseH + ((uint32_t)tt << 12));
        #pragma unroll
        for (int tt = 0; tt < 8; tt++)
            mma16816(&acc[4 * tt], &ahi[4 * s], wv[tt].x, wv[tt].y);   // Ahi*Whi
        #pragma unroll
        for (int tt = 0; tt < 8; tt++)
            mma16816(&acc[4 * tt], &ahi[4 * s], wv[tt].z, wv[tt].w);   // Ahi*Wlo
        #pragma unroll
        for (int tt = 0; tt < 8; tt++)
            mma16816(&acc[4 * tt], &alo[4 * s], wv[tt].x, wv[tt].y);   // Alo*Whi
    }

    float m0 = -1e30f, m1 = -1e30f;
    #pragma unroll
    for (int tt = 0; tt < 8; tt++) {
        int cb = 8 * tt + 2 * q;
        acc[4 * tt + 0] += bias[cb];     acc[4 * tt + 1] += bias[cb + 1];
        acc[4 * tt + 2] += bias[cb];     acc[4 * tt + 3] += bias[cb + 1];
        m0 = fmaxf(m0, fmaxf(acc[4 * tt + 0], acc[4 * tt + 1]));
        m1 = fmaxf(m1, fmaxf(acc[4 * tt + 2], acc[4 * tt + 3]));
    }
    m0 = fmaxf(m0, __shfl_xor_sync(0xffffffffu, m0, 1));
    m0 = fmaxf(m0, __shfl_xor_sync(0xffffffffu, m0, 2));
    m1 = fmaxf(m1, __shfl_xor_sync(0xffffffffu, m1, 1));
    m1 = fmaxf(m1, __shfl_xor_sync(0xffffffffu, m1, 2));
    float s0 = 0.0f, s1 = 0.0f;
    #pragma unroll
    for (int tt = 0; tt < 8; tt++) {
        s0 += __expf(acc[4 * tt + 0] - m0) + __expf(acc[4 * tt + 1] - m0);
        s1 += __expf(acc[4 * tt + 2] - m1) + __expf(acc[4 * tt + 3] - m1);
    }
    s0 += __shfl_xor_sync(0xffffffffu, s0, 1);
    s0 += __shfl_xor_sync(0xffffffffu, s0, 2);
    s1 += __shfl_xor_sync(0xffffffffu, s1, 1);
    s1 += __shfl_xor_sync(0xffffffffu, s1, 2);
    float lse0 = m0 + __logf(s0), lse1 = m1 + __logf(s1);
    #pragma unroll
    for (int tt = 0; tt < 8; tt++) {
        int cb = 8 * tt + 2 * q;
        float2 va = make_float2(acc[4 * tt + 0] - lse0, acc[4 * tt + 1] - lse0);
        float2 vb = make_float2(acc[4 * tt + 2] - lse1, acc[4 * tt + 3] - lse1);
        *reinterpret_cast<float2*>(out + (size_t)(row0 + r0l) * 64 + cb) = va;
        *reinterpret_cast<float2*>(out + (size_t)(row0 + r1l) * 64 + cb) = vb;
    }
}

// ---------------- gate pass (NT=4, double-buffered uint4 W prefetch; c0 from SMEM) ----------------
__device__ __forceinline__ void do_pass_g4(
    int tbase, char* sm, const float* __restrict__ bias,
    const uint32_t* ahi, const uint32_t* alo,
    int r0l, int r1l, int q, int l)
{
    float acc[16];
    #pragma unroll
    for (int i = 0; i < 16; i++) acc[i] = 0.0f;

    uint4 wv[2][4];
    const uint32_t base0 = (uint32_t)(tbase * 8) * 512u + (uint32_t)l * 16u;

    // prefetch s=0
    #pragma unroll
    for (int tt = 0; tt < 4; tt++)
        wv[0][tt] = *reinterpret_cast<const uint4*>(sm + OFF_W + base0 + ((uint32_t)tt << 12));

    #pragma unroll
    for (int s = 0; s < 8; s++) {
        const int cur = s & 1, nxt = cur ^ 1;
        if (s < 7) {                                  // prefetch s+1 while s computes
            uint32_t baseN = base0 + (uint32_t)(s + 1) * 512u;
            #pragma unroll
            for (int tt = 0; tt < 4; tt++)
                wv[nxt][tt] = *reinterpret_cast<const uint4*>(sm + OFF_W + baseN + ((uint32_t)tt << 12));
        }
        #pragma unroll
        for (int tt = 0; tt < 4; tt++)
            mma16816(&acc[4 * tt], &ahi[4 * s], wv[cur][tt].x, wv[cur][tt].y);   // Ahi*Whi
        #pragma unroll
        for (int tt = 0; tt < 4; tt++)
            mma16816(&acc[4 * tt], &ahi[4 * s], wv[cur][tt].z, wv[cur][tt].w);   // Ahi*Wlo
        #pragma unroll
        for (int tt = 0; tt < 4; tt++)
            mma16816(&acc[4 * tt], &alo[4 * s], wv[cur][tt].x, wv[cur][tt].y);   // Alo*Whi
    }

    // ---- gates: even lanes hold (i,f), odd (g,o) of same j; pair via shfl ----
    const bool even = ((q & 1) == 0);
    const float numer = even ? 1.0f : 2.0f;
    const float subv  = even ? 0.0f : 1.0f;
    const float scale = even ? -1.0f : -2.0f;
    #pragma unroll
    for (int tt = 0; tt < 4; tt++) {
        int t  = tbase + tt;
        int cb = 8 * t + 2 * q;
        float v0 = acc[4 * tt + 0] + bias[cb];
        float v1 = acc[4 * tt + 1] + bias[cb + 1];
        float v2 = acc[4 * tt + 2] + bias[cb];
        float v3 = acc[4 * tt + 3] + bias[cb + 1];
        float a0 = numer / (1.0f + __expf(scale * v0)) - subv;
        float a1 = 1.0f / (1.0f + __expf(-v1));
        float a2 = numer / (1.0f + __expf(scale * v2)) - subv;
        float a3 = 1.0f / (1.0f + __expf(-v3));
        float p0 = __shfl_xor_sync(0xffffffffu, a0, 1);
        float p1 = __shfl_xor_sync(0xffffffffu, a1, 1);
        float p2 = __shfl_xor_sync(0xffffffffu, a2, 1);
        float p3 = __shfl_xor_sync(0xffffffffu, a3, 1);
        if (even) {
            int jg = 2 * (t - 8) + (q >> 1);              // global col 0..63
            uint32_t co0 = (uint32_t)r0l * 256u + ((uint32_t)((jg >> 2) ^ (r0l & 7)) << 4) + ((uint32_t)(jg & 3) << 2);
            uint32_t co1 = (uint32_t)r1l * 256u + ((uint32_t)((jg >> 2) ^ (r1l & 7)) << 4) + ((uint32_t)(jg & 3) << 2);
            float c00 = *reinterpret_cast<const float*>(sm + OFF_C + co0);    // staged c0 (SMEM)
            float c11 = *reinterpret_cast<const float*>(sm + OFF_C + co1);
            float cn0 = a1 * c00 + a0 * p0;               // f*c + i*g
            float cn1 = a3 * c11 + a2 * p2;
            float hn0 = p1 * (2.0f / (1.0f + __expf(-2.0f * cn0)) - 1.0f);   // o*tanh(cn)
            float hn1 = p3 * (2.0f / (1.0f + __expf(-2.0f * cn1)) - 1.0f);
            *reinterpret_cast<float*>(sm + OFF_C + co0) = cn0;   // c_new in place
            *reinterpret_cast<float*>(sm + OFF_C + co1) = cn1;
            *reinterpret_cast<float*>(sm + OFF_H + co0) = hn0;
            *reinterpret_cast<float*>(sm + OFF_H + co1) = hn1;
        }
    }
}

__global__ __launch_bounds__(NTH, 1) void lstm_hmma_kernel(
    const float* __restrict__ x,   const float* __restrict__ h0,  const float* __restrict__ c0,
    const float* __restrict__ Wih, const float* __restrict__ Whh,
    const float* __restrict__ bih, const float* __restrict__ bhh,
    const float* __restrict__ Wo,  const float* __restrict__ bo,
    float* __restrict__ out)
{
    extern __shared__ __align__(16) char sm[];
    const uint32_t smb = smem_u32(sm);
    const int tid = threadIdx.x;
    const int w    = tid >> 5;
    const int l    = tid & 31;
    const int rg   = w & 7;            // row group 0..7 (16 rows each)
    const int half = w >> 3;           // n-half: 0 = z+gates j0..23, 1 = gates j24..63
    const int gr   = l >> 2;           // group row 0..7
    const int q    = l & 3;            // quad lane 0..3

    // ---- one-time: W -> interleaved (hi,lo) uint4 frags in SMEM ----
    for (int p = tid; p < 40 * 8 * 32; p += NTH) {
        int t = p >> 8, s = (p >> 5) & 7, ln = p & 31;
        int c = 8 * t + (ln >> 2);
        int k0 = 16 * s + 2 * (ln & 3);
        float w00 = getW(c, k0,     Wo, Wih, Whh);
        float w01 = getW(c, k0 + 1, Wo, Wih, Whh);
        float w10 = getW(c, k0 + 8, Wo, Wih, Whh);
        float w11 = getW(c, k0 + 9, Wo, Wih, Whh);
        uint32_t h0p, l0p, h1p, l1p;
        split2(w00, w01, h0p, l0p);   // b0: k0, k0+1
        split2(w10, w11, h1p, l1p);   // b1: k0+8, k0+9
        uint32_t base = (uint32_t)(t * 8 + s) * 512u + (uint32_t)ln * 16u;
        *reinterpret_cast<uint4*>(sm + OFF_W + base) = make_uint4(h0p, h1p, l0p, l1p);
    }
    // bias, same column reordering
    for (int c = tid; c < NTOT; c += NTH) {
        float b;
        if (c < 64) b = bo[c];
        else { int gc = c - 64, j = gc >> 2, g = gc & 3; b = bih[g * 64 + j] + bhh[g * 64 + j]; }
        reinterpret_cast<float*>(sm + OFF_BIAS)[c] = b;
    }
    __syncthreads();

    const float* bias = reinterpret_cast<const float*>(sm + OFF_BIAS);
    const int r0l = 16 * rg + gr, r1l = r0l + 8;

    for (int tile = blockIdx.x; tile < NTILES; tile += gridDim.x) {
        const int row0 = tile * TILE_M;

        // ---- c0 cp.async: column-split by half so completion is WARP-LOCAL ----
        // half0: cols j0..23 (chunks 0..5);  half1: cols j24..63 (chunks 6..15)
        if (half == 0) {
            for (int i = l; i < 16 * 6; i += 32) {
                int r16 = i / 6, jc = i % 6;
                int r = 16 * rg + r16;
                uint32_t dst = smb + OFF_C + (uint32_t)r * 256u + ((uint32_t)(jc ^ (r & 7)) << 4);
                cpa16(dst, c0 + (size_t)(row0 + r) * 64 + jc * 4);
            }
        } else {
            for (int i = l; i < 16 * 10; i += 32) {
                int r16 = i / 10, jc = 6 + i % 10;
                int r = 16 * rg + r16;
                uint32_t dst = smb + OFF_C + (uint32_t)r * 256u + ((uint32_t)(jc ^ (r & 7)) << 4);
                cpa16(dst, c0 + (size_t)(row0 + r) * 64 + jc * 4);
            }
        }
        CP_COMMIT();

        // ---- A tile: batched LDG (MLP=16 per half) -> split to hi/lo frags ----
        uint32_t ahi[32], alo[32];
        #pragma unroll
        for (int hb = 0; hb < 2; hb++) {               // hb=0: x (s 0..3), hb=1: h0 (s 4..7)
            const float* bp = hb ? h0 : x;
            float2 v[16];
            #pragma unroll
            for (int ss = 0; ss < 4; ss++) {           // issue all 16 loads first (deep MLP)
                int kf2 = 8 * ss + q;
                const float2* p0 = reinterpret_cast<const float2*>(bp) + (size_t)(row0 + r0l) * 32 + kf2;
                const float2* p1 = reinterpret_cast<const float2*>(bp) + (size_t)(row0 + r1l) * 32 + kf2;
                v[4 * ss + 0] = p0[0];
                v[4 * ss + 1] = p1[0];
                v[4 * ss + 2] = p0[4];
                v[4 * ss + 3] = p1[4];
            }
            #pragma unroll
            for (int ss = 0; ss < 4; ss++) {
                int s = 4 * hb + ss;
                split2(v[4 * ss + 0].x, v[4 * ss + 0].y, ahi[4 * s + 0], alo[4 * s + 0]);
                split2(v[4 * ss + 1].x, v[4 * ss + 1].y, ahi[4 * s + 1], alo[4 * s + 1]);
                split2(v[4 * ss + 2].x, v[4 * ss + 2].y, ahi[4 * s + 2], alo[4 * s + 2]);
                split2(v[4 * ss + 3].x, v[4 * ss + 3].y, ahi[4 * s + 3], alo[4 * s + 3]);
            }
        }

        // ---- warp-pair n-split: half0 = z + gates j0..23, half1 = gates j24..63 ----
        if (half == 0) {
            do_pass_z(sm, bias, ahi, alo, r0l, r1l, q, l, row0, out);
            CP_WAIT0();                 // this warp's own c0 chunks
            __syncwarp();
            do_pass_g4(8,  sm, bias, ahi, alo, r0l, r1l, q, l);
            do_pass_g4(12, sm, bias, ahi, alo, r0l, r1l, q, l);
            do_pass_g4(16, sm, bias, ahi, alo, r0l, r1l, q, l);
        } else {
            CP_WAIT0();
            __syncwarp();
            do_pass_g4(20, sm, bias, ahi, alo, r0l, r1l, q, l);
            do_pass_g4(24, sm, bias, ahi, alo, r0l, r1l, q, l);
            do_pass_g4(28, sm, bias, ahi, alo, r0l, r1l, q, l);
            do_pass_g4(32, sm, bias, ahi, alo, r0l, r1l, q, l);
            do_pass_g4(36, sm, bias, ahi, alo, r0l, r1l, q, l);
        }

        // ---- one barrier, then fully vectorized h/c stores ----
        __syncthreads();
        #pragma unroll
        for (int i = 0; i < 4; i++) {
            int p = tid + i * NTH;                     // 0..2047
            int r = p >> 4, c4 = p & 15;
            uint32_t off = (uint32_t)r * 256u + ((uint32_t)(c4 ^ (r & 7)) << 4);
            float4 hv = *reinterpret_cast<const float4*>(sm + OFF_H + off);
            float4 cv = *reinterpret_cast<const float4*>(sm + OFF_C + off);
            size_t g = (size_t)(row0 + r) * 64 + (size_t)c4 * 4;
            *reinterpret_cast<float4*>(out + (size_t)B_ROWS * 64 + g)     = hv;
            *reinterpret_cast<float4*>(out + (size_t)2 * B_ROWS * 64 + g) = cv;
        }
        __syncthreads();   // protect OFF_H/OFF_C before next tile's cp.async / writes
    }
}

extern "C" void kernel_launch(void* const* d_in, const int* in_sizes, int n_in,
                              void* d_out, int out_size) {
    (void)in_sizes; (void)n_in; (void)out_size;
    cudaFuncSetAttribute(lstm_hmma_kernel, cudaFuncAttributeMaxDynamicSharedMemorySize, SMEM_BYTES);
    lstm_hmma_kernel<<<GRID, NTH, SMEM_BYTES>>>(
        (const float*)d_in[0], (const float*)d_in[1], (const float*)d_in[2],
        (const float*)d_in[3], (const float*)d_in[4],
        (const float*)d_in[5], (const float*)d_in[6],
        (const float*)d_in[7], (const float*)d_in[8],
        (float*)d_out);
}